// round 5
// baseline (speedup 1.0000x reference)
#include <cuda_runtime.h>
#include <math.h>

// Problem dims (fixed by the dataset)
#define BB 32
#define DD 1024
#define HH 1024

#define GEMM_BLOCKS 32        // h-tiles of 32: 1024/32
#define STREAM_BLOCKS 1024    // stride 262144 f4; 2^23/262144 = 32 iters exact
#define NTHREADS 256
#define N4 ((BB*DD*HH)/4)     // 8388608 float4

// d_out layout (float32, reference return order):
//   out   [B,H]      @ 0
//   u_new [B,H]      @ 32768
//   E_w   [B,D,H]    @ 65536
//   E_b   [B,H]      @ 65536 + 33554432
#define OFF_UNEW (BB*HH)
#define OFF_EW   (2*BB*HH)
#define OFF_EB   (2*BB*HH + BB*DD*HH)

__global__ void diag_rtrl_fused_kernel(
    const float* __restrict__ x,   // [B,D]
    const float* __restrict__ w,   // [D,H]
    const float* __restrict__ b,   // [H]
    const float* __restrict__ u,   // [B,H]
    const float* __restrict__ Ew,  // [1,B,D,H]
    const float* __restrict__ Eb,  // [1,B,H]
    float* __restrict__ out)       // packed outputs
{
    if (blockIdx.x >= GEMM_BLOCKS) {
        // ---------------- E_w streaming path ----------------
        // E_new_w[i,d,h] = 0.9*E_w[i,d,h] + x[i,d]
        // float4 index p -> element 4p -> x index (4p)>>10 = p>>8
        const float4* __restrict__ ein = reinterpret_cast<const float4*>(Ew);
        float4* __restrict__ eo = reinterpret_cast<float4*>(&out[OFF_EW]);

        constexpr int stride = STREAM_BLOCKS * NTHREADS;  // 262144 (const imm)
        int p = (blockIdx.x - GEMM_BLOCKS) * NTHREADS + threadIdx.x;

        // 8 outer iterations x MLP=4 front-batched loads, no reg cap
        #pragma unroll 1
        for (int it = 0; it < 8; it++) {
            // four independent 16B loads: addresses are p + const*stride
            float4 e0 = __ldcs(ein + p);
            float4 e1 = __ldcs(ein + p + stride);
            float4 e2 = __ldcs(ein + p + 2 * stride);
            float4 e3 = __ldcs(ein + p + 3 * stride);
            float x0 = __ldg(&x[p >> 8]);
            float x1 = __ldg(&x[(p + stride) >> 8]);
            float x2 = __ldg(&x[(p + 2 * stride) >> 8]);
            float x3 = __ldg(&x[(p + 3 * stride) >> 8]);

            float4 r0, r1, r2, r3;
            r0.x = fmaf(0.9f, e0.x, x0); r0.y = fmaf(0.9f, e0.y, x0);
            r0.z = fmaf(0.9f, e0.z, x0); r0.w = fmaf(0.9f, e0.w, x0);
            r1.x = fmaf(0.9f, e1.x, x1); r1.y = fmaf(0.9f, e1.y, x1);
            r1.z = fmaf(0.9f, e1.z, x1); r1.w = fmaf(0.9f, e1.w, x1);
            r2.x = fmaf(0.9f, e2.x, x2); r2.y = fmaf(0.9f, e2.y, x2);
            r2.z = fmaf(0.9f, e2.z, x2); r2.w = fmaf(0.9f, e2.w, x2);
            r3.x = fmaf(0.9f, e3.x, x3); r3.y = fmaf(0.9f, e3.y, x3);
            r3.z = fmaf(0.9f, e3.z, x3); r3.w = fmaf(0.9f, e3.w, x3);

            __stcs(eo + p, r0);
            __stcs(eo + p + stride, r1);
            __stcs(eo + p + 2 * stride, r2);
            __stcs(eo + p + 3 * stride, r3);

            p += 4 * stride;
        }
    } else {
        // ---------------- GEMM + epilogue path ----------------
        // block handles h-tile of 32 columns, all 32 batch rows.
        __shared__ float xs[32][33];                 // [i][k] (+pad)
        __shared__ __align__(16) float ws[32][32];   // [k][h]

        const int t  = threadIdx.x;
        const int h0 = blockIdx.x * 32;
        const int hx = t & 7;           // which float4 of the 32-h tile
        const int i  = t >> 3;          // batch row 0..31

        float4 acc = make_float4(0.f, 0.f, 0.f, 0.f);

        for (int kt = 0; kt < DD; kt += 32) {
            // x tile: 32 rows x 32 k (coalesced)
            for (int m = t; m < 1024; m += NTHREADS)
                xs[m >> 5][m & 31] = x[(m >> 5) * DD + kt + (m & 31)];
            // w tile: 32 k x 32 h (coalesced)
            for (int m = t; m < 1024; m += NTHREADS)
                ws[m >> 5][m & 31] = w[(kt + (m >> 5)) * HH + h0 + (m & 31)];
            __syncthreads();

            #pragma unroll 8
            for (int k = 0; k < 32; k++) {
                float4 wv = reinterpret_cast<const float4*>(&ws[k][0])[hx];
                float xv = xs[i][k];
                acc.x = fmaf(xv, wv.x, acc.x);
                acc.y = fmaf(xv, wv.y, acc.y);
                acc.z = fmaf(xv, wv.z, acc.z);
                acc.w = fmaf(xv, wv.w, acc.w);
            }
            __syncthreads();
        }

        // epilogue: z = 0.9*u + x@w + b ; out = tanh(z); u_new = z; E_b
        const int h   = h0 + hx * 4;
        const int idx = i * HH + h;
        float4 bv = *reinterpret_cast<const float4*>(&b[h]);
        float4 uv = *reinterpret_cast<const float4*>(&u[idx]);
        float4 z;
        z.x = fmaf(0.9f, uv.x, acc.x + bv.x);
        z.y = fmaf(0.9f, uv.y, acc.y + bv.y);
        z.z = fmaf(0.9f, uv.z, acc.z + bv.z);
        z.w = fmaf(0.9f, uv.w, acc.w + bv.w);

        *reinterpret_cast<float4*>(&out[OFF_UNEW + idx]) = z;

        float4 o;
        o.x = tanhf(z.x); o.y = tanhf(z.y);
        o.z = tanhf(z.z); o.w = tanhf(z.w);
        *reinterpret_cast<float4*>(&out[idx]) = o;

        float4 ev = *reinterpret_cast<const float4*>(&Eb[idx]);
        float4 e;
        e.x = fmaf(0.9f, ev.x, 1.0f);
        e.y = fmaf(0.9f, ev.y, 1.0f);
        e.z = fmaf(0.9f, ev.z, 1.0f);
        e.w = fmaf(0.9f, ev.w, 1.0f);
        *reinterpret_cast<float4*>(&out[OFF_EB + idx]) = e;
    }
}

extern "C" void kernel_launch(void* const* d_in, const int* in_sizes, int n_in,
                              void* d_out, int out_size) {
    const float* x  = (const float*)d_in[0];  // [32,1024]
    const float* w  = (const float*)d_in[1];  // [1024,1024]
    const float* b  = (const float*)d_in[2];  // [1024]
    const float* u  = (const float*)d_in[3];  // [32,1024]
    const float* Ew = (const float*)d_in[4];  // [1,32,1024,1024]
    const float* Eb = (const float*)d_in[5];  // [1,32,1024]
    float* out = (float*)d_out;

    diag_rtrl_fused_kernel<<<GEMM_BLOCKS + STREAM_BLOCKS, NTHREADS>>>(
        x, w, b, u, Ew, Eb, out);
}